// round 15
// baseline (speedup 1.0000x reference)
#include <cuda_runtime.h>

#define BB    32
#define CINC  32
#define COUTC 32
#define TT    2048
#define DKK   32
#define NFFT  4096
#define FH    2064   // half-spectrum row stride (f = 0..2048 valid; 16-float2 aligned)

// FFT dynamic smem: 4096-pt buffer + 256-entry twiddle table
#define FFT_SMEM_BYTES ((NFFT + 256) * sizeof(float2))   // 34816

// pointwise dynamic smem: 2 buffers x (2048 X + 1024 G) float2
#define PW_SMEM_BYTES (2 * 3072 * sizeof(float2))        // 49152

// smem bank-conflict swizzle for the FFT buffer (float2 index domain)
#define SW(i) ((i) ^ ((((i) >> 4) & 15)))

// ---- scratch (device globals; allocation-free) -----------------------------
__device__ float  g_buf[COUTC * CINC * TT];   // [o*32+i][d]   8 MB
__device__ float2 Xf[1024 * FH];              // [b*32+i][f]
__device__ float2 Gf[1024 * FH];              // [o*32+i][f]
__device__ float2 Of[1024 * FH];              // [b*32+o][f]

__device__ __forceinline__ float2 cmulf(float2 a, float2 b) {
    return make_float2(a.x * b.x - a.y * b.y, a.x * b.y + a.y * b.x);
}
__device__ __forceinline__ float2 caddf(float2 a, float2 b) { return make_float2(a.x + b.x, a.y + b.y); }
__device__ __forceinline__ float2 csubf(float2 a, float2 b) { return make_float2(a.x - b.x, a.y - b.y); }

// packed f32x2 helpers (Blackwell FFMA2)
typedef unsigned long long ull;
__device__ __forceinline__ ull pk2(float lo, float hi) {
    ull d; asm("mov.b64 %0, {%1, %2};" : "=l"(d) : "f"(lo), "f"(hi)); return d;
}
__device__ __forceinline__ void upk2(float& lo, float& hi, ull v) {
    asm("mov.b64 {%0, %1}, %2;" : "=f"(lo), "=f"(hi) : "l"(v));
}
__device__ __forceinline__ ull fma2(ull a, ull b, ull c) {
    ull d; asm("fma.rn.f32x2 %0, %1, %2, %3;" : "=l"(d) : "l"(a), "l"(b), "l"(c)); return d;
}

// cp.async helpers (LDGSTS)
__device__ __forceinline__ void cpasync16(unsigned int dst_smem, const void* src) {
    asm volatile("cp.async.cg.shared.global [%0], [%1], 16;"
                 :: "r"(dst_smem), "l"(src) : "memory");
}
#define CP_COMMIT() asm volatile("cp.async.commit_group;" ::: "memory")
#define CP_WAIT(n)  asm volatile("cp.async.wait_group %0;" :: "n"(n) : "memory")

// ---------------------------------------------------------------------------
// 16-point DFT codelet (registers only, in place).
// ---------------------------------------------------------------------------
template<bool INV>
__device__ __forceinline__ void dft16(float2* a) {
    const float c1 = 0.92387953251128675613f;
    const float s1 = 0.38268343236508977173f;
    const float Cc = 0.70710678118654752440f;
    float2 B[16];
#pragma unroll
    for (int n0 = 0; n0 < 4; n0++) {
        float2 p0 = a[n0], p1 = a[4 + n0], p2 = a[8 + n0], p3 = a[12 + n0];
        float2 t0 = caddf(p0, p2), t1 = csubf(p0, p2);
        float2 t2 = caddf(p1, p3), t3 = csubf(p1, p3);
        float2 t3r = INV ? make_float2(-t3.y, t3.x) : make_float2(t3.y, -t3.x);
        B[n0 * 4 + 0] = caddf(t0, t2);
        B[n0 * 4 + 1] = caddf(t1, t3r);
        B[n0 * 4 + 2] = csubf(t0, t2);
        B[n0 * 4 + 3] = csubf(t1, t3r);
    }
    const float sg = INV ? 1.f : -1.f;
    const float2 w1 = make_float2(c1, sg * s1);
    const float2 w2 = make_float2(Cc, sg * Cc);
    const float2 w3 = make_float2(s1, sg * c1);
    const float2 w6 = make_float2(-Cc, sg * Cc);
    const float2 w9 = make_float2(-c1, -sg * s1);
    B[5]  = cmulf(B[5],  w1);
    B[6]  = cmulf(B[6],  w2);
    B[7]  = cmulf(B[7],  w3);
    B[9]  = cmulf(B[9],  w2);
    B[10] = INV ? make_float2(-B[10].y, B[10].x) : make_float2(B[10].y, -B[10].x);
    B[11] = cmulf(B[11], w6);
    B[13] = cmulf(B[13], w3);
    B[14] = cmulf(B[14], w6);
    B[15] = cmulf(B[15], w9);
#pragma unroll
    for (int r0 = 0; r0 < 4; r0++) {
        float2 p0 = B[r0], p1 = B[4 + r0], p2 = B[8 + r0], p3 = B[12 + r0];
        float2 t0 = caddf(p0, p2), t1 = csubf(p0, p2);
        float2 t2 = caddf(p1, p3), t3 = csubf(p1, p3);
        float2 t3r = INV ? make_float2(-t3.y, t3.x) : make_float2(t3.y, -t3.x);
        a[r0]      = caddf(t0, t2);
        a[4 + r0]  = caddf(t1, t3r);
        a[8 + r0]  = csubf(t0, t2);
        a[12 + r0] = csubf(t1, t3r);
    }
}

// ---------------------------------------------------------------------------
// SIREN MLP -> g_buf.  g[o,i,d] = kern[o,i,2048-d], d in [0,2048).
// ---------------------------------------------------------------------------
__global__ void __launch_bounds__(256)
gen_kernel(const float* __restrict__ rel_pos,
           const float* __restrict__ w1,
           const float* __restrict__ b1,
           const float* __restrict__ omega1p,
           const float* __restrict__ w2,
           const float* __restrict__ b2,
           const float* __restrict__ omega2p,
           const float* __restrict__ w3,
           const float* __restrict__ b3) {
    __shared__ float h2s[128][33];
    __shared__ float w3s[128][32];
    __shared__ float b3s[128];
    const int tid = threadIdx.x;
    const int j2b0 = blockIdx.y * 128;

#pragma unroll
    for (int q = 0; q < 4; q++) {
        int flat4 = tid + 256 * q;
        int row = flat4 >> 3;
        int c4  = flat4 & 7;
        ((float4*)&w3s[row][0])[c4] = ((const float4*)(w3 + (size_t)(j2b0 + row) * 32))[c4];
    }
    if (tid < 128) b3s[tid] = b3[j2b0 + tid];

    if (tid < 128) {
        const int kl = tid;
        const int k  = 1 + blockIdx.x * 128 + kl;
        const float pos = rel_pos[k];
        const float o1 = *omega1p, o2 = *omega2p;
        float h1[DKK];
#pragma unroll
        for (int j = 0; j < DKK; j++)
            h1[j] = sinf(o1 * (w1[j] * pos + b1[j]));
        for (int j = 0; j < DKK; j++) {
            float a = b2[j];
#pragma unroll
            for (int l = 0; l < DKK; l++)
                a += w2[j * DKK + l] * h1[l];
            h2s[kl][j] = sinf(o2 * a);
        }
    }
    __syncthreads();

    const int kl   = tid & 127;
    const int half = tid >> 7;
    const int k    = 1 + blockIdx.x * 128 + kl;
    const int d    = 2048 - k;
    float h2r[32];
#pragma unroll
    for (int l = 0; l < 32; l++) h2r[l] = h2s[kl][l];

    for (int jj = 0; jj < 64; jj++) {
        const int row = half * 64 + jj;
        float a = b3s[row];
#pragma unroll
        for (int l4 = 0; l4 < 8; l4++) {
            float4 w = ((const float4*)&w3s[row][0])[l4];
            a += w.x * h2r[4*l4+0] + w.y * h2r[4*l4+1]
               + w.z * h2r[4*l4+2] + w.w * h2r[4*l4+3];
        }
        g_buf[(size_t)(j2b0 + row) * TT + d] = a;
    }
}

// ---------------------------------------------------------------------------
// 4096-pt radix-16 Stockham FFT (3 stages), packed-real, one pair per block.
// (R8 version: chained twiddles, direct global loads stage 0, direct stores inv)
// FWD (INV=false): gsel=0 -> x rows -> Xf ; gsel=1 -> g rows -> Gf
// ---------------------------------------------------------------------------
template<bool INV>
__global__ void __launch_bounds__(256, 4)
fft4096_kernel(const float* __restrict__ rsrc,
               float* __restrict__ rdst,
               const float* __restrict__ bias,
               int gsel) {
    extern __shared__ float2 dyn[];
    float2* buf = dyn;                 // NFFT (swizzled indexing)
    float2* tws = dyn + NFFT;          // 256
    const int tid = threadIdx.x;

    const int sig = blockIdx.x;               // pair index in [0,512)
    const int isG = INV ? 0 : gsel;
    const int hb  = sig >> 4;
    const int ip  = sig & 15;
    const int rowA = hb * 32 + 2 * ip;

    float sv, cv;
    sincospif(-(float)tid / 2048.0f, &sv, &cv);
    tws[tid] = make_float2(cv, sv);

    // ---- stage 0: registers straight from global --------------------------
    float2 a[16];
    if (!INV) {
        const float* baseA = isG ? (g_buf + (size_t)rowA * TT)
                                 : (rsrc + (size_t)rowA * TT);
        const float* baseB = baseA + TT;
#pragma unroll
        for (int r = 0; r < 8; r++) {
            int idx = tid + 256 * r;
            a[r] = make_float2(baseA[idx], baseB[idx]);
        }
#pragma unroll
        for (int r = 8; r < 16; r++) a[r] = make_float2(0.f, 0.f);   // folded
    } else {
        const float2* srcA = Of + (size_t)rowA * FH;
        const float2* srcB = srcA + FH;
#pragma unroll
        for (int r = 0; r < 16; r++) {
            int f = tid + 256 * r;
            if (f <= 2048) {
                float2 o1 = srcA[f], o2 = srcB[f];
                a[r] = make_float2(o1.x - o2.y, o1.y + o2.x);
            } else {
                int fp = NFFT - f;               // 1..2047, reversed-coalesced
                float2 o1 = srcA[fp], o2 = srcB[fp];
                a[r] = make_float2(o1.x + o2.y, o2.x - o1.y);
            }
        }
    }
    dft16<INV>(a);
    {   // jm = tid, k = 0, m = 1 -> own twiddle, no table dependency
        float2 W1 = make_float2(cv, INV ? -sv : sv);
        const int wb = 16 * tid;
        buf[SW(wb)] = a[0];
        float2 Wc = W1;
#pragma unroll
        for (int r = 1; r < 16; r++) {
            buf[SW(wb + r)] = cmulf(a[r], Wc);
            Wc = cmulf(Wc, W1);
        }
    }
    __syncthreads();

    // ---- stage 1: smem -> smem (m = 16) ------------------------------------
    {
#pragma unroll
        for (int r = 0; r < 16; r++) a[r] = buf[SW(tid + 256 * r)];
        __syncthreads();
        dft16<INV>(a);
        const int k  = tid & 15;
        const int jm = tid - k;
        const int wb = 16 * jm + k;
        float2 W1 = tws[jm];
        if (INV) W1.y = -W1.y;
        buf[SW(wb)] = a[0];
        float2 Wc = W1;
#pragma unroll
        for (int r = 1; r < 16; r++) {
            buf[SW(wb + 16 * r)] = cmulf(a[r], Wc);
            Wc = cmulf(Wc, W1);
        }
        __syncthreads();
    }

    // ---- stage 2: smem -> registers (m = 256; jm = 0, no twiddles) --------
#pragma unroll
    for (int r = 0; r < 16; r++) a[r] = buf[SW(tid + 256 * r)];
    dft16<INV>(a);

    if (!INV) {
        __syncthreads();
#pragma unroll
        for (int r = 0; r < 16; r++) buf[SW(tid + 256 * r)] = a[r];
        __syncthreads();
        float2* dstA = (isG ? Gf : Xf) + (size_t)rowA * FH;
        float2* dstB = dstA + FH;
#pragma unroll
        for (int q = 0; q < 8; q++) {
            int f  = tid + 256 * q;              // 0..2047
            int fm = (NFFT - f) & (NFFT - 1);
            float2 z  = buf[SW(f)];
            float2 zm = buf[SW(fm)];
            dstA[f] = make_float2(0.5f * (z.x + zm.x), 0.5f * (z.y - zm.y));
            dstB[f] = make_float2(0.5f * (z.y + zm.y), 0.5f * (zm.x - z.x));
        }
        if (tid == 0) {
            float2 z = buf[SW(2048)];
            dstA[2048] = make_float2(z.x, 0.f);
            dstB[2048] = make_float2(z.y, 0.f);
        }
    } else {
        const float sc = 1.0f / (float)NFFT;
        const float bv1 = bias[(rowA) & 31];
        const float bv2 = bias[(rowA + 1) & 31];
        float* dst1 = rdst + (size_t)rowA * TT;
        float* dst2 = dst1 + TT;
#pragma unroll
        for (int r = 0; r < 8; r++) {
            int t = tid + 256 * r;
            dst1[t] = a[r].x * sc + bv1;
            dst2[t] = a[r].y * sc + bv2;
        }
    }
}

// ---------------------------------------------------------------------------
// Pointwise complex GEMM (cp.async double-buffer + o-split for 2 blocks/SM):
//   Of[b,o,f] = sum_i Xf[b,i,f] * Gf[o,i,f]
// grid (129, 2) = (f-tile 16, o-half 16), 512 threads, all 32 b per block.
// Thread (ff, oog<8 -> 2 o's, bg<4 -> 8 b's): acc[2][8] (32 regs).
// Dynamic smem: buffer k at k*3072 float2: [0..2048) X, [2048..3072) G.
// ---------------------------------------------------------------------------
__global__ void __launch_bounds__(512, 2)
pointwise_kernel() {
    extern __shared__ float2 pws[];
    const int tid = threadIdx.x;
    const int f0  = blockIdx.x * 16;
    const int o0  = blockIdx.y * 16;
    const int ff  = tid & 15;
    const int oo0 = ((tid >> 4) & 7) * 2;   // 8 groups x 2 o = 16 o
    const int bb0 = (tid >> 7) * 8;         // 4 groups x 8 b = 32 b

    const unsigned int sbase = (unsigned int)__cvta_generic_to_shared(pws);

    // stage chunk (4 i's starting at ic) into buffer `bsel` via cp.async
    auto stage = [&](int ic, int bsel) {
        unsigned int xb = sbase + bsel * 3072 * 8;         // float2 = 8 bytes
        unsigned int gb = xb + 2048 * 8;
        // X: 1024 float4 (all 32 b), 2 per thread
#pragma unroll
        for (int q = 0; q < 2; q++) {
            int flat4 = tid + 512 * q;        // = ii*256 + rr*8 + f4
            int f4 = flat4 & 7;
            int rr = (flat4 >> 3) & 31;
            int ii = flat4 >> 8;
            int row = rr * 32 + ic + ii;      // b*32+i
            cpasync16(xb + flat4 * 16, ((const float4*)(Xf + (size_t)row * FH + f0)) + f4);
        }
        // G: 512 float4 (this block's 16 o's), 1 per thread
        {
            int f4 = tid & 7;
            int rr = (tid >> 3) & 15;
            int ii = tid >> 7;
            int row = (o0 + rr) * 32 + ic + ii;   // o*32+i
            cpasync16(gb + tid * 16, ((const float4*)(Gf + (size_t)row * FH + f0)) + f4);
        }
        CP_COMMIT();
    };

    ull acc[2][8];
#pragma unroll
    for (int j = 0; j < 2; j++)
#pragma unroll
        for (int l = 0; l < 8; l++) acc[j][l] = 0ull;

    stage(0, 0);   // prime buffer 0

    for (int c = 0; c < 8; c++) {
        const int bsel = c & 1;
        if (c < 7) {
            stage((c + 1) * 4, bsel ^ 1);
            CP_WAIT(1);          // chunk c's group complete (c+1 may remain)
        } else {
            CP_WAIT(0);
        }
        __syncthreads();

        const float2* Xs = pws + bsel * 3072;
        const float2* Gs = Xs + 2048;
#pragma unroll
        for (int ii = 0; ii < 4; ii++) {
            ull gp[2], gq[2];
#pragma unroll
            for (int j = 0; j < 2; j++) {
                float2 g = Gs[(ii * 16 + oo0 + j) * 16 + ff];
                gp[j] = pk2(g.x, g.y);
                gq[j] = pk2(-g.y, g.x);
            }
#pragma unroll
            for (int l = 0; l < 8; l++) {
                float2 xv = Xs[(ii * 32 + bb0 + l) * 16 + ff];
                ull bx = pk2(xv.x, xv.x);
                ull by = pk2(xv.y, xv.y);
#pragma unroll
                for (int j = 0; j < 2; j++) {
                    acc[j][l] = fma2(bx, gp[j], acc[j][l]);
                    acc[j][l] = fma2(by, gq[j], acc[j][l]);
                }
            }
        }
        __syncthreads();         // all reads of this buffer done before re-stage
    }

#pragma unroll
    for (int j = 0; j < 2; j++)
#pragma unroll
        for (int l = 0; l < 8; l++) {
            float2 v;
            upk2(v.x, v.y, acc[j][l]);
            Of[(size_t)((bb0 + l) * 32 + o0 + oo0 + j) * FH + f0 + ff] = v;
        }
}

// ---------------------------------------------------------------------------
// Forked-capture launch graph:
//   main:  xFFT ─────────────┐
//   s2:    gen → gFFT ───────┴→ pointwise → invFFT
// ---------------------------------------------------------------------------
extern "C" void kernel_launch(void* const* d_in, const int* in_sizes, int n_in,
                              void* d_out, int out_size) {
    const float* x       = (const float*)d_in[0];
    const float* rel_pos = (const float*)d_in[1];
    const float* w1      = (const float*)d_in[2];
    const float* b1      = (const float*)d_in[3];
    const float* omega1  = (const float*)d_in[4];
    const float* w2      = (const float*)d_in[5];
    const float* b2      = (const float*)d_in[6];
    const float* omega2  = (const float*)d_in[7];
    const float* w3      = (const float*)d_in[8];
    const float* b3      = (const float*)d_in[9];
    const float* bias    = (const float*)d_in[10];
    float* out = (float*)d_out;

    static cudaStream_t s2 = nullptr;
    static cudaEvent_t eFork = nullptr, eJoin = nullptr;
    if (s2 == nullptr) {   // created on the (non-captured) correctness call
        cudaStreamCreateWithFlags(&s2, cudaStreamNonBlocking);
        cudaEventCreateWithFlags(&eFork, cudaEventDisableTiming);
        cudaEventCreateWithFlags(&eJoin, cudaEventDisableTiming);
        cudaFuncSetAttribute(pointwise_kernel,
                             cudaFuncAttributeMaxDynamicSharedMemorySize, PW_SMEM_BYTES);
    }

    // fork: s2 branches off the main (capturing) stream
    cudaEventRecord(eFork, 0);
    cudaStreamWaitEvent(s2, eFork, 0);

    // side branch: gen -> g-FFT
    gen_kernel<<<dim3(16, 8), 256, 0, s2>>>(rel_pos, w1, b1, omega1, w2, b2, omega2, w3, b3);
    fft4096_kernel<false><<<512, 256, FFT_SMEM_BYTES, s2>>>(nullptr, nullptr, nullptr, 1); // g->Gf

    // main branch: x-FFT (independent of gen)
    fft4096_kernel<false><<<512, 256, FFT_SMEM_BYTES>>>(x, nullptr, nullptr, 0);           // x->Xf

    // join: main waits for the side branch
    cudaEventRecord(eJoin, s2);
    cudaStreamWaitEvent(0, eJoin, 0);

    pointwise_kernel<<<dim3(129, 2), 512, PW_SMEM_BYTES>>>();                              // Xf*Gf -> Of
    fft4096_kernel<true><<<512, 256, FFT_SMEM_BYTES>>>(nullptr, out, bias, 0);             // Of -> out
}

// round 16
// speedup vs baseline: 1.0573x; 1.0573x over previous
#include <cuda_runtime.h>

#define BB    32
#define CINC  32
#define COUTC 32
#define TT    2048
#define DKK   32
#define NFFT  4096
#define FH    2064   // half-spectrum row stride (f = 0..2048 valid; 16-float2 aligned)

// FFT dynamic smem: 4096-pt buffer + 256-entry twiddle table
#define FFT_SMEM_BYTES ((NFFT + 256) * sizeof(float2))   // 34816

// pointwise dynamic smem: 4 buffers x (2048 X + 2048 G) float2
#define PW_SMEM_BYTES (4 * 4096 * sizeof(float2))        // 131072

// smem bank-conflict swizzle for the FFT buffer (float2 index domain)
#define SW(i) ((i) ^ ((((i) >> 4) & 15)))

// ---- scratch (device globals; allocation-free) -----------------------------
__device__ float  g_buf[COUTC * CINC * TT];   // [o*32+i][d]   8 MB
__device__ float2 Xf[1024 * FH];              // [b*32+i][f]
__device__ float2 Gf[1024 * FH];              // [o*32+i][f]
__device__ float2 Of[1024 * FH];              // [b*32+o][f]

__device__ __forceinline__ float2 cmulf(float2 a, float2 b) {
    return make_float2(a.x * b.x - a.y * b.y, a.x * b.y + a.y * b.x);
}
__device__ __forceinline__ float2 caddf(float2 a, float2 b) { return make_float2(a.x + b.x, a.y + b.y); }
__device__ __forceinline__ float2 csubf(float2 a, float2 b) { return make_float2(a.x - b.x, a.y - b.y); }

// packed f32x2 helpers (Blackwell FFMA2)
typedef unsigned long long ull;
__device__ __forceinline__ ull pk2(float lo, float hi) {
    ull d; asm("mov.b64 %0, {%1, %2};" : "=l"(d) : "f"(lo), "f"(hi)); return d;
}
__device__ __forceinline__ void upk2(float& lo, float& hi, ull v) {
    asm("mov.b64 {%0, %1}, %2;" : "=f"(lo), "=f"(hi) : "l"(v));
}
__device__ __forceinline__ ull fma2(ull a, ull b, ull c) {
    ull d; asm("fma.rn.f32x2 %0, %1, %2, %3;" : "=l"(d) : "l"(a), "l"(b), "l"(c)); return d;
}

// cp.async helpers (LDGSTS)
__device__ __forceinline__ void cpasync16(unsigned int dst_smem, const void* src) {
    asm volatile("cp.async.cg.shared.global [%0], [%1], 16;"
                 :: "r"(dst_smem), "l"(src) : "memory");
}
#define CP_COMMIT() asm volatile("cp.async.commit_group;" ::: "memory")
#define CP_WAIT(n)  asm volatile("cp.async.wait_group %0;" :: "n"(n) : "memory")

// ---------------------------------------------------------------------------
// 16-point DFT codelet (registers only, in place).
// ---------------------------------------------------------------------------
template<bool INV>
__device__ __forceinline__ void dft16(float2* a) {
    const float c1 = 0.92387953251128675613f;
    const float s1 = 0.38268343236508977173f;
    const float Cc = 0.70710678118654752440f;
    float2 B[16];
#pragma unroll
    for (int n0 = 0; n0 < 4; n0++) {
        float2 p0 = a[n0], p1 = a[4 + n0], p2 = a[8 + n0], p3 = a[12 + n0];
        float2 t0 = caddf(p0, p2), t1 = csubf(p0, p2);
        float2 t2 = caddf(p1, p3), t3 = csubf(p1, p3);
        float2 t3r = INV ? make_float2(-t3.y, t3.x) : make_float2(t3.y, -t3.x);
        B[n0 * 4 + 0] = caddf(t0, t2);
        B[n0 * 4 + 1] = caddf(t1, t3r);
        B[n0 * 4 + 2] = csubf(t0, t2);
        B[n0 * 4 + 3] = csubf(t1, t3r);
    }
    const float sg = INV ? 1.f : -1.f;
    const float2 w1 = make_float2(c1, sg * s1);
    const float2 w2 = make_float2(Cc, sg * Cc);
    const float2 w3 = make_float2(s1, sg * c1);
    const float2 w6 = make_float2(-Cc, sg * Cc);
    const float2 w9 = make_float2(-c1, -sg * s1);
    B[5]  = cmulf(B[5],  w1);
    B[6]  = cmulf(B[6],  w2);
    B[7]  = cmulf(B[7],  w3);
    B[9]  = cmulf(B[9],  w2);
    B[10] = INV ? make_float2(-B[10].y, B[10].x) : make_float2(B[10].y, -B[10].x);
    B[11] = cmulf(B[11], w6);
    B[13] = cmulf(B[13], w3);
    B[14] = cmulf(B[14], w6);
    B[15] = cmulf(B[15], w9);
#pragma unroll
    for (int r0 = 0; r0 < 4; r0++) {
        float2 p0 = B[r0], p1 = B[4 + r0], p2 = B[8 + r0], p3 = B[12 + r0];
        float2 t0 = caddf(p0, p2), t1 = csubf(p0, p2);
        float2 t2 = caddf(p1, p3), t3 = csubf(p1, p3);
        float2 t3r = INV ? make_float2(-t3.y, t3.x) : make_float2(t3.y, -t3.x);
        a[r0]      = caddf(t0, t2);
        a[4 + r0]  = caddf(t1, t3r);
        a[8 + r0]  = csubf(t0, t2);
        a[12 + r0] = csubf(t1, t3r);
    }
}

// ---------------------------------------------------------------------------
// SIREN MLP -> g_buf.  g[o,i,d] = kern[o,i,2048-d], d in [0,2048).
// ---------------------------------------------------------------------------
__global__ void __launch_bounds__(256)
gen_kernel(const float* __restrict__ rel_pos,
           const float* __restrict__ w1,
           const float* __restrict__ b1,
           const float* __restrict__ omega1p,
           const float* __restrict__ w2,
           const float* __restrict__ b2,
           const float* __restrict__ omega2p,
           const float* __restrict__ w3,
           const float* __restrict__ b3) {
    __shared__ float h2s[128][33];
    __shared__ float w3s[128][32];
    __shared__ float b3s[128];
    const int tid = threadIdx.x;
    const int j2b0 = blockIdx.y * 128;

#pragma unroll
    for (int q = 0; q < 4; q++) {
        int flat4 = tid + 256 * q;
        int row = flat4 >> 3;
        int c4  = flat4 & 7;
        ((float4*)&w3s[row][0])[c4] = ((const float4*)(w3 + (size_t)(j2b0 + row) * 32))[c4];
    }
    if (tid < 128) b3s[tid] = b3[j2b0 + tid];

    if (tid < 128) {
        const int kl = tid;
        const int k  = 1 + blockIdx.x * 128 + kl;
        const float pos = rel_pos[k];
        const float o1 = *omega1p, o2 = *omega2p;
        float h1[DKK];
#pragma unroll
        for (int j = 0; j < DKK; j++)
            h1[j] = sinf(o1 * (w1[j] * pos + b1[j]));
        for (int j = 0; j < DKK; j++) {
            float a = b2[j];
#pragma unroll
            for (int l = 0; l < DKK; l++)
                a += w2[j * DKK + l] * h1[l];
            h2s[kl][j] = sinf(o2 * a);
        }
    }
    __syncthreads();

    const int kl   = tid & 127;
    const int half = tid >> 7;
    const int k    = 1 + blockIdx.x * 128 + kl;
    const int d    = 2048 - k;
    float h2r[32];
#pragma unroll
    for (int l = 0; l < 32; l++) h2r[l] = h2s[kl][l];

    for (int jj = 0; jj < 64; jj++) {
        const int row = half * 64 + jj;
        float a = b3s[row];
#pragma unroll
        for (int l4 = 0; l4 < 8; l4++) {
            float4 w = ((const float4*)&w3s[row][0])[l4];
            a += w.x * h2r[4*l4+0] + w.y * h2r[4*l4+1]
               + w.z * h2r[4*l4+2] + w.w * h2r[4*l4+3];
        }
        g_buf[(size_t)(j2b0 + row) * TT + d] = a;
    }
}

// ---------------------------------------------------------------------------
// 4096-pt radix-16 Stockham FFT (3 stages), packed-real, one pair per block.
// (R8 version: chained twiddles, direct global loads stage 0, direct stores inv)
// FWD (INV=false): gsel=0 -> x rows -> Xf ; gsel=1 -> g rows -> Gf
// ---------------------------------------------------------------------------
template<bool INV>
__global__ void __launch_bounds__(256, 4)
fft4096_kernel(const float* __restrict__ rsrc,
               float* __restrict__ rdst,
               const float* __restrict__ bias,
               int gsel) {
    extern __shared__ float2 dyn[];
    float2* buf = dyn;                 // NFFT (swizzled indexing)
    float2* tws = dyn + NFFT;          // 256
    const int tid = threadIdx.x;

    const int sig = blockIdx.x;               // pair index in [0,512)
    const int isG = INV ? 0 : gsel;
    const int hb  = sig >> 4;
    const int ip  = sig & 15;
    const int rowA = hb * 32 + 2 * ip;

    float sv, cv;
    sincospif(-(float)tid / 2048.0f, &sv, &cv);
    tws[tid] = make_float2(cv, sv);

    // ---- stage 0: registers straight from global --------------------------
    float2 a[16];
    if (!INV) {
        const float* baseA = isG ? (g_buf + (size_t)rowA * TT)
                                 : (rsrc + (size_t)rowA * TT);
        const float* baseB = baseA + TT;
#pragma unroll
        for (int r = 0; r < 8; r++) {
            int idx = tid + 256 * r;
            a[r] = make_float2(baseA[idx], baseB[idx]);
        }
#pragma unroll
        for (int r = 8; r < 16; r++) a[r] = make_float2(0.f, 0.f);   // folded
    } else {
        const float2* srcA = Of + (size_t)rowA * FH;
        const float2* srcB = srcA + FH;
#pragma unroll
        for (int r = 0; r < 16; r++) {
            int f = tid + 256 * r;
            if (f <= 2048) {
                float2 o1 = srcA[f], o2 = srcB[f];
                a[r] = make_float2(o1.x - o2.y, o1.y + o2.x);
            } else {
                int fp = NFFT - f;               // 1..2047, reversed-coalesced
                float2 o1 = srcA[fp], o2 = srcB[fp];
                a[r] = make_float2(o1.x + o2.y, o2.x - o1.y);
            }
        }
    }
    dft16<INV>(a);
    {   // jm = tid, k = 0, m = 1 -> own twiddle, no table dependency
        float2 W1 = make_float2(cv, INV ? -sv : sv);
        const int wb = 16 * tid;
        buf[SW(wb)] = a[0];
        float2 Wc = W1;
#pragma unroll
        for (int r = 1; r < 16; r++) {
            buf[SW(wb + r)] = cmulf(a[r], Wc);
            Wc = cmulf(Wc, W1);
        }
    }
    __syncthreads();

    // ---- stage 1: smem -> smem (m = 16) ------------------------------------
    {
#pragma unroll
        for (int r = 0; r < 16; r++) a[r] = buf[SW(tid + 256 * r)];
        __syncthreads();
        dft16<INV>(a);
        const int k  = tid & 15;
        const int jm = tid - k;
        const int wb = 16 * jm + k;
        float2 W1 = tws[jm];
        if (INV) W1.y = -W1.y;
        buf[SW(wb)] = a[0];
        float2 Wc = W1;
#pragma unroll
        for (int r = 1; r < 16; r++) {
            buf[SW(wb + 16 * r)] = cmulf(a[r], Wc);
            Wc = cmulf(Wc, W1);
        }
        __syncthreads();
    }

    // ---- stage 2: smem -> registers (m = 256; jm = 0, no twiddles) --------
#pragma unroll
    for (int r = 0; r < 16; r++) a[r] = buf[SW(tid + 256 * r)];
    dft16<INV>(a);

    if (!INV) {
        __syncthreads();
#pragma unroll
        for (int r = 0; r < 16; r++) buf[SW(tid + 256 * r)] = a[r];
        __syncthreads();
        float2* dstA = (isG ? Gf : Xf) + (size_t)rowA * FH;
        float2* dstB = dstA + FH;
#pragma unroll
        for (int q = 0; q < 8; q++) {
            int f  = tid + 256 * q;              // 0..2047
            int fm = (NFFT - f) & (NFFT - 1);
            float2 z  = buf[SW(f)];
            float2 zm = buf[SW(fm)];
            dstA[f] = make_float2(0.5f * (z.x + zm.x), 0.5f * (z.y - zm.y));
            dstB[f] = make_float2(0.5f * (z.y + zm.y), 0.5f * (zm.x - z.x));
        }
        if (tid == 0) {
            float2 z = buf[SW(2048)];
            dstA[2048] = make_float2(z.x, 0.f);
            dstB[2048] = make_float2(z.y, 0.f);
        }
    } else {
        const float sc = 1.0f / (float)NFFT;
        const float bv1 = bias[(rowA) & 31];
        const float bv2 = bias[(rowA + 1) & 31];
        float* dst1 = rdst + (size_t)rowA * TT;
        float* dst2 = dst1 + TT;
#pragma unroll
        for (int r = 0; r < 8; r++) {
            int t = tid + 256 * r;
            dst1[t] = a[r].x * sc + bv1;
            dst2[t] = a[r].y * sc + bv2;
        }
    }
}

// ---------------------------------------------------------------------------
// Pointwise complex GEMM (R13 tile + 4-buffer cp.async, ONE barrier/chunk):
//   Of[b,o,f] = sum_i Xf[b,i,f] * Gf[o,i,f]
// grid (129), 512 threads; block = all 32 b x 32 o for a 16-wide f tile.
// Buffer k at k*4096 float2: [0..2048) X, [2048..4096) G.
// Iter c: wait(c done) -> sync -> compute(c) -> stage(c+3).
// Overwrite safety: buffer (c+3)&3 was last read in compute(c-1); every
// thread passed the iter-c barrier AFTER its compute(c-1).
// ---------------------------------------------------------------------------
__global__ void __launch_bounds__(512)
pointwise_kernel() {
    extern __shared__ float2 pws[];
    const int tid = threadIdx.x;
    const int f0  = blockIdx.x * 16;
    const int ff  = tid & 15;
    const int oo0 = ((tid >> 4) & 7) * 4;
    const int bb0 = (tid >> 7) * 8;

    const unsigned int sbase = (unsigned int)__cvta_generic_to_shared(pws);

    // stage chunk (4 i's starting at ic) into buffer `bsel` via cp.async
    auto stage = [&](int ic, int bsel) {
        unsigned int xb = sbase + bsel * 4096 * 8;         // float2 = 8 bytes
        unsigned int gb = xb + 2048 * 8;
#pragma unroll
        for (int q = 0; q < 2; q++) {
            int flat4 = tid + 512 * q;        // = ii*256 + rr*8 + f4
            int f4 = flat4 & 7;
            int rr = (flat4 >> 3) & 31;
            int ii = flat4 >> 8;
            int row = rr * 32 + ic + ii;      // b*32+i  (== o*32+i)
            cpasync16(xb + flat4 * 16, ((const float4*)(Xf + (size_t)row * FH + f0)) + f4);
            cpasync16(gb + flat4 * 16, ((const float4*)(Gf + (size_t)row * FH + f0)) + f4);
        }
        CP_COMMIT();
    };

    ull acc[4][8];
#pragma unroll
    for (int j = 0; j < 4; j++)
#pragma unroll
        for (int l = 0; l < 8; l++) acc[j][l] = 0ull;

    stage(0, 0);
    stage(4, 1);
    stage(8, 2);

    for (int c = 0; c < 8; c++) {
        const int bsel = c & 3;
        // wait until chunk c's group has landed (exact pending counts at tail)
        if (c < 5)      CP_WAIT(2);
        else if (c == 5) CP_WAIT(2);
        else if (c == 6) CP_WAIT(1);
        else             CP_WAIT(0);
        __syncthreads();    // publish all threads' cp.async data; also fences
                            // compute(c-1) before buffer (c+3)&3 is re-staged

        const float2* Xs = pws + bsel * 4096;
        const float2* Gs = Xs + 2048;
#pragma unroll
        for (int ii = 0; ii < 4; ii++) {
            ull gp[4], gq[4];
#pragma unroll
            for (int j = 0; j < 4; j++) {
                float2 g = Gs[(ii * 32 + oo0 + j) * 16 + ff];
                gp[j] = pk2(g.x, g.y);
                gq[j] = pk2(-g.y, g.x);
            }
#pragma unroll
            for (int l = 0; l < 8; l++) {
                float2 xv = Xs[(ii * 32 + bb0 + l) * 16 + ff];
                ull bx = pk2(xv.x, xv.x);
                ull by = pk2(xv.y, xv.y);
#pragma unroll
                for (int j = 0; j < 4; j++) {
                    acc[j][l] = fma2(bx, gp[j], acc[j][l]);
                    acc[j][l] = fma2(by, gq[j], acc[j][l]);
                }
            }
        }

        if (c < 5) stage((c + 3) * 4, (c + 3) & 3);
    }

#pragma unroll
    for (int j = 0; j < 4; j++)
#pragma unroll
        for (int l = 0; l < 8; l++) {
            float2 v;
            upk2(v.x, v.y, acc[j][l]);
            Of[(size_t)((bb0 + l) * 32 + oo0 + j) * FH + f0 + ff] = v;
        }
}

// ---------------------------------------------------------------------------
// Forked-capture launch graph:
//   main:  xFFT ─────────────┐
//   s2:    gen → gFFT ───────┴→ pointwise → invFFT
// ---------------------------------------------------------------------------
extern "C" void kernel_launch(void* const* d_in, const int* in_sizes, int n_in,
                              void* d_out, int out_size) {
    const float* x       = (const float*)d_in[0];
    const float* rel_pos = (const float*)d_in[1];
    const float* w1      = (const float*)d_in[2];
    const float* b1      = (const float*)d_in[3];
    const float* omega1  = (const float*)d_in[4];
    const float* w2      = (const float*)d_in[5];
    const float* b2      = (const float*)d_in[6];
    const float* omega2  = (const float*)d_in[7];
    const float* w3      = (const float*)d_in[8];
    const float* b3      = (const float*)d_in[9];
    const float* bias    = (const float*)d_in[10];
    float* out = (float*)d_out;

    static cudaStream_t s2 = nullptr;
    static cudaEvent_t eFork = nullptr, eJoin = nullptr;
    if (s2 == nullptr) {   // created on the (non-captured) correctness call
        cudaStreamCreateWithFlags(&s2, cudaStreamNonBlocking);
        cudaEventCreateWithFlags(&eFork, cudaEventDisableTiming);
        cudaEventCreateWithFlags(&eJoin, cudaEventDisableTiming);
        cudaFuncSetAttribute(pointwise_kernel,
                             cudaFuncAttributeMaxDynamicSharedMemorySize, PW_SMEM_BYTES);
    }

    // fork: s2 branches off the main (capturing) stream
    cudaEventRecord(eFork, 0);
    cudaStreamWaitEvent(s2, eFork, 0);

    // side branch: gen -> g-FFT
    gen_kernel<<<dim3(16, 8), 256, 0, s2>>>(rel_pos, w1, b1, omega1, w2, b2, omega2, w3, b3);
    fft4096_kernel<false><<<512, 256, FFT_SMEM_BYTES, s2>>>(nullptr, nullptr, nullptr, 1); // g->Gf

    // main branch: x-FFT (independent of gen)
    fft4096_kernel<false><<<512, 256, FFT_SMEM_BYTES>>>(x, nullptr, nullptr, 0);           // x->Xf

    // join: main waits for the side branch
    cudaEventRecord(eJoin, s2);
    cudaStreamWaitEvent(0, eJoin, 0);

    pointwise_kernel<<<129, 512, PW_SMEM_BYTES>>>();                                       // Xf*Gf -> Of
    fft4096_kernel<true><<<512, 256, FFT_SMEM_BYTES>>>(nullptr, out, bias, 0);             // Of -> out
}

// round 17
// speedup vs baseline: 1.1034x; 1.0436x over previous
#include <cuda_runtime.h>

#define BB    32
#define CINC  32
#define COUTC 32
#define TT    2048
#define DKK   32
#define NFFT  4096
#define FH    2064   // half-spectrum row stride (f = 0..2048 valid; 16-float2 aligned)

// FFT dynamic smem: 4096-pt buffer + 256-entry twiddle table
#define FFT_SMEM_BYTES ((NFFT + 256) * sizeof(float2))   // 34816

// pointwise dynamic smem: 4 buffers x (2048 X + 2048 G) float2
#define PW_SMEM_BYTES (4 * 4096 * sizeof(float2))        // 131072

// smem bank-conflict swizzle for the FFT buffer (float2 index domain)
#define SW(i) ((i) ^ ((((i) >> 4) & 15)))

// ---- scratch (device globals; allocation-free) -----------------------------
__device__ float  g_buf[COUTC * CINC * TT];   // [o*32+i][d]   8 MB
__device__ float2 Xf[1024 * FH];              // [b*32+i][f]
__device__ float2 Gf[1024 * FH];              // [o*32+i][f]
__device__ float2 Of[1024 * FH];              // [b*32+o][f]

__device__ __forceinline__ float2 cmulf(float2 a, float2 b) {
    return make_float2(a.x * b.x - a.y * b.y, a.x * b.y + a.y * b.x);
}
__device__ __forceinline__ float2 caddf(float2 a, float2 b) { return make_float2(a.x + b.x, a.y + b.y); }
__device__ __forceinline__ float2 csubf(float2 a, float2 b) { return make_float2(a.x - b.x, a.y - b.y); }

// packed f32x2 helpers (Blackwell FFMA2)
typedef unsigned long long ull;
__device__ __forceinline__ ull pk2(float lo, float hi) {
    ull d; asm("mov.b64 %0, {%1, %2};" : "=l"(d) : "f"(lo), "f"(hi)); return d;
}
__device__ __forceinline__ void upk2(float& lo, float& hi, ull v) {
    asm("mov.b64 {%0, %1}, %2;" : "=f"(lo), "=f"(hi) : "l"(v));
}
__device__ __forceinline__ ull fma2(ull a, ull b, ull c) {
    ull d; asm("fma.rn.f32x2 %0, %1, %2, %3;" : "=l"(d) : "l"(a), "l"(b), "l"(c)); return d;
}

// cp.async helpers (LDGSTS)
__device__ __forceinline__ void cpasync16(unsigned int dst_smem, const void* src) {
    asm volatile("cp.async.cg.shared.global [%0], [%1], 16;"
                 :: "r"(dst_smem), "l"(src) : "memory");
}
#define CP_COMMIT() asm volatile("cp.async.commit_group;" ::: "memory")
#define CP_WAIT(n)  asm volatile("cp.async.wait_group %0;" :: "n"(n) : "memory")

// PDL intrinsics (no-ops when kernel not launched with the PDL attribute)
__device__ __forceinline__ void pdl_sync()    { cudaGridDependencySynchronize(); }
__device__ __forceinline__ void pdl_trigger() { cudaTriggerProgrammaticLaunchCompletion(); }

// ---------------------------------------------------------------------------
// 16-point DFT codelet (registers only, in place).
// ---------------------------------------------------------------------------
template<bool INV>
__device__ __forceinline__ void dft16(float2* a) {
    const float c1 = 0.92387953251128675613f;
    const float s1 = 0.38268343236508977173f;
    const float Cc = 0.70710678118654752440f;
    float2 B[16];
#pragma unroll
    for (int n0 = 0; n0 < 4; n0++) {
        float2 p0 = a[n0], p1 = a[4 + n0], p2 = a[8 + n0], p3 = a[12 + n0];
        float2 t0 = caddf(p0, p2), t1 = csubf(p0, p2);
        float2 t2 = caddf(p1, p3), t3 = csubf(p1, p3);
        float2 t3r = INV ? make_float2(-t3.y, t3.x) : make_float2(t3.y, -t3.x);
        B[n0 * 4 + 0] = caddf(t0, t2);
        B[n0 * 4 + 1] = caddf(t1, t3r);
        B[n0 * 4 + 2] = csubf(t0, t2);
        B[n0 * 4 + 3] = csubf(t1, t3r);
    }
    const float sg = INV ? 1.f : -1.f;
    const float2 w1 = make_float2(c1, sg * s1);
    const float2 w2 = make_float2(Cc, sg * Cc);
    const float2 w3 = make_float2(s1, sg * c1);
    const float2 w6 = make_float2(-Cc, sg * Cc);
    const float2 w9 = make_float2(-c1, -sg * s1);
    B[5]  = cmulf(B[5],  w1);
    B[6]  = cmulf(B[6],  w2);
    B[7]  = cmulf(B[7],  w3);
    B[9]  = cmulf(B[9],  w2);
    B[10] = INV ? make_float2(-B[10].y, B[10].x) : make_float2(B[10].y, -B[10].x);
    B[11] = cmulf(B[11], w6);
    B[13] = cmulf(B[13], w3);
    B[14] = cmulf(B[14], w6);
    B[15] = cmulf(B[15], w9);
#pragma unroll
    for (int r0 = 0; r0 < 4; r0++) {
        float2 p0 = B[r0], p1 = B[4 + r0], p2 = B[8 + r0], p3 = B[12 + r0];
        float2 t0 = caddf(p0, p2), t1 = csubf(p0, p2);
        float2 t2 = caddf(p1, p3), t3 = csubf(p1, p3);
        float2 t3r = INV ? make_float2(-t3.y, t3.x) : make_float2(t3.y, -t3.x);
        a[r0]      = caddf(t0, t2);
        a[4 + r0]  = caddf(t1, t3r);
        a[8 + r0]  = csubf(t0, t2);
        a[12 + r0] = csubf(t1, t3r);
    }
}

// Two-chain twiddle store: odd powers W1,W3..W15 and even W2,W4..W14,
// each stepping by W2 (recurrence depth ~8 instead of 15).
template<bool INV>
__device__ __forceinline__ void store_tw(float2* buf, const float2* a,
                                         int wb, int m, float2 W1) {
    float2 W2 = cmulf(W1, W1);
    buf[SW(wb)] = a[0];
    float2 Wo = W1;
    buf[SW(wb + m)] = cmulf(a[1], Wo);
    float2 We = W2;
    buf[SW(wb + 2 * m)] = cmulf(a[2], We);
#pragma unroll
    for (int r = 3; r < 16; r += 2) {
        Wo = cmulf(Wo, W2);
        buf[SW(wb + r * m)] = cmulf(a[r], Wo);
    }
#pragma unroll
    for (int r = 4; r < 16; r += 2) {
        We = cmulf(We, W2);
        buf[SW(wb + r * m)] = cmulf(a[r], We);
    }
}

// ---------------------------------------------------------------------------
// SIREN MLP -> g_buf.  g[o,i,d] = kern[o,i,2048-d], d in [0,2048).
// ---------------------------------------------------------------------------
__global__ void __launch_bounds__(256)
gen_kernel(const float* __restrict__ rel_pos,
           const float* __restrict__ w1,
           const float* __restrict__ b1,
           const float* __restrict__ omega1p,
           const float* __restrict__ w2,
           const float* __restrict__ b2,
           const float* __restrict__ omega2p,
           const float* __restrict__ w3,
           const float* __restrict__ b3) {
    __shared__ float h2s[128][33];
    __shared__ float w3s[128][32];
    __shared__ float b3s[128];
    const int tid = threadIdx.x;
    const int j2b0 = blockIdx.y * 128;

#pragma unroll
    for (int q = 0; q < 4; q++) {
        int flat4 = tid + 256 * q;
        int row = flat4 >> 3;
        int c4  = flat4 & 7;
        ((float4*)&w3s[row][0])[c4] = ((const float4*)(w3 + (size_t)(j2b0 + row) * 32))[c4];
    }
    if (tid < 128) b3s[tid] = b3[j2b0 + tid];

    if (tid < 128) {
        const int kl = tid;
        const int k  = 1 + blockIdx.x * 128 + kl;
        const float pos = rel_pos[k];
        const float o1 = *omega1p, o2 = *omega2p;
        float h1[DKK];
#pragma unroll
        for (int j = 0; j < DKK; j++)
            h1[j] = sinf(o1 * (w1[j] * pos + b1[j]));
        for (int j = 0; j < DKK; j++) {
            float a = b2[j];
#pragma unroll
            for (int l = 0; l < DKK; l++)
                a += w2[j * DKK + l] * h1[l];
            h2s[kl][j] = sinf(o2 * a);
        }
    }
    __syncthreads();

    const int kl   = tid & 127;
    const int half = tid >> 7;
    const int k    = 1 + blockIdx.x * 128 + kl;
    const int d    = 2048 - k;
    float h2r[32];
#pragma unroll
    for (int l = 0; l < 32; l++) h2r[l] = h2s[kl][l];

    for (int jj = 0; jj < 64; jj++) {
        const int row = half * 64 + jj;
        float a = b3s[row];
#pragma unroll
        for (int l4 = 0; l4 < 8; l4++) {
            float4 w = ((const float4*)&w3s[row][0])[l4];
            a += w.x * h2r[4*l4+0] + w.y * h2r[4*l4+1]
               + w.z * h2r[4*l4+2] + w.w * h2r[4*l4+3];
        }
        g_buf[(size_t)(j2b0 + row) * TT + d] = a;
    }
    pdl_trigger();   // g_buf rows written; dependent (gFFT) may launch
}

// ---------------------------------------------------------------------------
// 4096-pt radix-16 Stockham FFT (3 stages), packed-real, one pair per block.
// (R8 structure; two-chain twiddles; PDL prologue before upstream reads)
// FWD (INV=false): gsel=0 -> x rows -> Xf ; gsel=1 -> g rows -> Gf
// ---------------------------------------------------------------------------
template<bool INV>
__global__ void __launch_bounds__(256, 4)
fft4096_kernel(const float* __restrict__ rsrc,
               float* __restrict__ rdst,
               const float* __restrict__ bias,
               int gsel) {
    extern __shared__ float2 dyn[];
    float2* buf = dyn;                 // NFFT (swizzled indexing)
    float2* tws = dyn + NFFT;          // 256
    const int tid = threadIdx.x;

    const int sig = blockIdx.x;               // pair index in [0,512)
    const int isG = INV ? 0 : gsel;
    const int hb  = sig >> 4;
    const int ip  = sig & 15;
    const int rowA = hb * 32 + 2 * ip;

    // prologue (upstream-independent): twiddle compute + table store
    float sv, cv;
    sincospif(-(float)tid / 2048.0f, &sv, &cv);
    tws[tid] = make_float2(cv, sv);

    pdl_sync();   // upstream grid complete before reading its buffers

    // ---- stage 0: registers straight from global --------------------------
    float2 a[16];
    if (!INV) {
        const float* baseA = isG ? (g_buf + (size_t)rowA * TT)
                                 : (rsrc + (size_t)rowA * TT);
        const float* baseB = baseA + TT;
#pragma unroll
        for (int r = 0; r < 8; r++) {
            int idx = tid + 256 * r;
            a[r] = make_float2(baseA[idx], baseB[idx]);
        }
#pragma unroll
        for (int r = 8; r < 16; r++) a[r] = make_float2(0.f, 0.f);   // folded
    } else {
        const float2* srcA = Of + (size_t)rowA * FH;
        const float2* srcB = srcA + FH;
#pragma unroll
        for (int r = 0; r < 16; r++) {
            int f = tid + 256 * r;
            if (f <= 2048) {
                float2 o1 = srcA[f], o2 = srcB[f];
                a[r] = make_float2(o1.x - o2.y, o1.y + o2.x);
            } else {
                int fp = NFFT - f;               // 1..2047, reversed-coalesced
                float2 o1 = srcA[fp], o2 = srcB[fp];
                a[r] = make_float2(o1.x + o2.y, o2.x - o1.y);
            }
        }
    }
    dft16<INV>(a);
    // jm = tid, k = 0, m = 1 -> own twiddle, no table dependency
    store_tw<INV>(buf, a, 16 * tid, 1, make_float2(cv, INV ? -sv : sv));
    __syncthreads();

    // ---- stage 1: smem -> smem (m = 16) ------------------------------------
    {
#pragma unroll
        for (int r = 0; r < 16; r++) a[r] = buf[SW(tid + 256 * r)];
        __syncthreads();
        dft16<INV>(a);
        const int k  = tid & 15;
        const int jm = tid - k;
        float2 W1 = tws[jm];
        if (INV) W1.y = -W1.y;
        store_tw<INV>(buf, a, 16 * jm + k, 16, W1);
        __syncthreads();
    }

    // ---- stage 2: smem -> registers (m = 256; jm = 0, no twiddles) --------
#pragma unroll
    for (int r = 0; r < 16; r++) a[r] = buf[SW(tid + 256 * r)];
    dft16<INV>(a);

    if (!INV) {
        __syncthreads();
#pragma unroll
        for (int r = 0; r < 16; r++) buf[SW(tid + 256 * r)] = a[r];
        __syncthreads();
        float2* dstA = (isG ? Gf : Xf) + (size_t)rowA * FH;
        float2* dstB = dstA + FH;
#pragma unroll
        for (int q = 0; q < 8; q++) {
            int f  = tid + 256 * q;              // 0..2047
            int fm = (NFFT - f) & (NFFT - 1);
            float2 z  = buf[SW(f)];
            float2 zm = buf[SW(fm)];
            dstA[f] = make_float2(0.5f * (z.x + zm.x), 0.5f * (z.y - zm.y));
            dstB[f] = make_float2(0.5f * (z.y + zm.y), 0.5f * (zm.x - z.x));
        }
        if (tid == 0) {
            float2 z = buf[SW(2048)];
            dstA[2048] = make_float2(z.x, 0.f);
            dstB[2048] = make_float2(z.y, 0.f);
        }
    } else {
        const float sc = 1.0f / (float)NFFT;
        const float bv1 = bias[(rowA) & 31];
        const float bv2 = bias[(rowA + 1) & 31];
        float* dst1 = rdst + (size_t)rowA * TT;
        float* dst2 = dst1 + TT;
#pragma unroll
        for (int r = 0; r < 8; r++) {
            int t = tid + 256 * r;
            dst1[t] = a[r].x * sc + bv1;
            dst2[t] = a[r].y * sc + bv2;
        }
    }
    pdl_trigger();
}

// ---------------------------------------------------------------------------
// Pointwise complex GEMM (FROZEN R13/R15 form: 4-buffer cp.async pipeline):
//   Of[b,o,f] = sum_i Xf[b,i,f] * Gf[o,i,f]
// ---------------------------------------------------------------------------
__global__ void __launch_bounds__(512)
pointwise_kernel() {
    extern __shared__ float2 pws[];
    const int tid = threadIdx.x;
    const int f0  = blockIdx.x * 16;
    const int ff  = tid & 15;
    const int oo0 = ((tid >> 4) & 7) * 4;
    const int bb0 = (tid >> 7) * 8;

    const unsigned int sbase = (unsigned int)__cvta_generic_to_shared(pws);

    auto stage = [&](int ic, int bsel) {
        unsigned int xb = sbase + bsel * 4096 * 8;
        unsigned int gb = xb + 2048 * 8;
#pragma unroll
        for (int q = 0; q < 2; q++) {
            int flat4 = tid + 512 * q;        // = ii*256 + rr*8 + f4
            int f4 = flat4 & 7;
            int rr = (flat4 >> 3) & 31;
            int ii = flat4 >> 8;
            int row = rr * 32 + ic + ii;      // b*32+i  (== o*32+i)
            cpasync16(xb + flat4 * 16, ((const float4*)(Xf + (size_t)row * FH + f0)) + f4);
            cpasync16(gb + flat4 * 16, ((const float4*)(Gf + (size_t)row * FH + f0)) + f4);
        }
        CP_COMMIT();
    };

    ull acc[4][8];
#pragma unroll
    for (int j = 0; j < 4; j++)
#pragma unroll
        for (int l = 0; l < 8; l++) acc[j][l] = 0ull;

    pdl_sync();   // Xf/Gf complete before first cp.async

    stage(0, 0);
    stage(4, 1);
    stage(8, 2);

    for (int c = 0; c < 8; c++) {
        const int bsel = c & 3;
        if (c < 6)       CP_WAIT(2);
        else if (c == 6) CP_WAIT(1);
        else             CP_WAIT(0);
        __syncthreads();

        const float2* Xs = pws + bsel * 4096;
        const float2* Gs = Xs + 2048;
#pragma unroll
        for (int ii = 0; ii < 4; ii++) {
            ull gp[4], gq[4];
#pragma unroll
            for (int j = 0; j < 4; j++) {
                float2 g = Gs[(ii * 32 + oo0 + j) * 16 + ff];
                gp[j] = pk2(g.x, g.y);
                gq[j] = pk2(-g.y, g.x);
            }
#pragma unroll
            for (int l = 0; l < 8; l++) {
                float2 xv = Xs[(ii * 32 + bb0 + l) * 16 + ff];
                ull bx = pk2(xv.x, xv.x);
                ull by = pk2(xv.y, xv.y);
#pragma unroll
                for (int j = 0; j < 4; j++) {
                    acc[j][l] = fma2(bx, gp[j], acc[j][l]);
                    acc[j][l] = fma2(by, gq[j], acc[j][l]);
                }
            }
        }

        if (c < 5) stage((c + 3) * 4, (c + 3) & 3);
    }

#pragma unroll
    for (int j = 0; j < 4; j++)
#pragma unroll
        for (int l = 0; l < 8; l++) {
            float2 v;
            upk2(v.x, v.y, acc[j][l]);
            Of[(size_t)((bb0 + l) * 32 + oo0 + j) * FH + f0 + ff] = v;
        }
    pdl_trigger();   // Of written; inverse FFT may launch
}

// ---------------------------------------------------------------------------
// Forked-capture launch graph with PDL on the serialized edges:
//   main:  xFFT ─────────────┐
//   s2:    gen →(PDL) gFFT ──┴→(PDL) pointwise →(PDL) invFFT
// ---------------------------------------------------------------------------
extern "C" void kernel_launch(void* const* d_in, const int* in_sizes, int n_in,
                              void* d_out, int out_size) {
    const float* x       = (const float*)d_in[0];
    const float* rel_pos = (const float*)d_in[1];
    const float* w1      = (const float*)d_in[2];
    const float* b1      = (const float*)d_in[3];
    const float* omega1  = (const float*)d_in[4];
    const float* w2      = (const float*)d_in[5];
    const float* b2      = (const float*)d_in[6];
    const float* omega2  = (const float*)d_in[7];
    const float* w3      = (const float*)d_in[8];
    const float* b3      = (const float*)d_in[9];
    const float* bias    = (const float*)d_in[10];
    float* out = (float*)d_out;

    static cudaStream_t s2 = nullptr;
    static cudaEvent_t eFork = nullptr, eJoin = nullptr;
    if (s2 == nullptr) {   // created on the (non-captured) correctness call
        cudaStreamCreateWithFlags(&s2, cudaStreamNonBlocking);
        cudaEventCreateWithFlags(&eFork, cudaEventDisableTiming);
        cudaEventCreateWithFlags(&eJoin, cudaEventDisableTiming);
        cudaFuncSetAttribute(pointwise_kernel,
                             cudaFuncAttributeMaxDynamicSharedMemorySize, PW_SMEM_BYTES);
    }

    cudaLaunchAttribute pdlAttr[1];
    pdlAttr[0].id = cudaLaunchAttributeProgrammaticStreamSerialization;
    pdlAttr[0].val.programmaticStreamSerializationAllowed = 1;

    // fork: s2 branches off the main (capturing) stream
    cudaEventRecord(eFork, 0);
    cudaStreamWaitEvent(s2, eFork, 0);

    // side branch: gen -> (PDL) gFFT
    gen_kernel<<<dim3(16, 8), 256, 0, s2>>>(rel_pos, w1, b1, omega1, w2, b2, omega2, w3, b3);
    {
        cudaLaunchConfig_t cfg = {};
        cfg.gridDim = dim3(512); cfg.blockDim = dim3(256);
        cfg.dynamicSmemBytes = FFT_SMEM_BYTES; cfg.stream = s2;
        cfg.attrs = pdlAttr; cfg.numAttrs = 1;
        cudaLaunchKernelEx(&cfg, fft4096_kernel<false>,
                           (const float*)nullptr, (float*)nullptr,
                           (const float*)nullptr, 1);                 // g->Gf
    }

    // main branch: x-FFT (independent of gen; no PDL needed)
    fft4096_kernel<false><<<512, 256, FFT_SMEM_BYTES>>>(x, nullptr, nullptr, 0);   // x->Xf

    // join: main waits for the side branch
    cudaEventRecord(eJoin, s2);
    cudaStreamWaitEvent(0, eJoin, 0);

    {   // pointwise with PDL (overlaps xFFT tail on the main stream)
        cudaLaunchConfig_t cfg = {};
        cfg.gridDim = dim3(129); cfg.blockDim = dim3(512);
        cfg.dynamicSmemBytes = PW_SMEM_BYTES; cfg.stream = 0;
        cfg.attrs = pdlAttr; cfg.numAttrs = 1;
        cudaLaunchKernelEx(&cfg, pointwise_kernel);                   // Xf*Gf -> Of
    }
    {   // inverse FFT with PDL (prologue overlaps pointwise tail)
        cudaLaunchConfig_t cfg = {};
        cfg.gridDim = dim3(512); cfg.blockDim = dim3(256);
        cfg.dynamicSmemBytes = FFT_SMEM_BYTES; cfg.stream = 0;
        cfg.attrs = pdlAttr; cfg.numAttrs = 1;
        cudaLaunchKernelEx(&cfg, fft4096_kernel<true>,
                           (const float*)nullptr, out, bias, 0);      // Of -> out
    }
}